// round 8
// baseline (speedup 1.0000x reference)
#include <cuda_runtime.h>

// BloomStageLoss: label-smoothed CE + transition penalty, reduced to scalar.
// inputs:  d_in[0] = float32 [B,5], d_in[1] = int32 [B]; output: float32 [1]
//
// loss_row = lse - 0.875*x_t - 0.025*sum(x)
//          + 0.1*(2 - (2*e_t + 1.5*(e_{t-1}+e_{t+1}) + (e_{t-2}+e_{t+2}))/se)

#define TGT_W     0.875f
#define SMOOTH_W  0.025f
#define TPEN      0.1f

__device__ float        g_acc;        // zero-init at module load; reset by last block each replay
__device__ unsigned int g_count;

// Returns lse - 0.875*x_t - 0.1*u/se  (caller adds -0.025*grand_sum and +0.2/row)
__device__ __forceinline__ float row_core(float x0, float x1, float x2, float x3, float x4, int t) {
    float e0 = __expf(x0), e1 = __expf(x1), e2 = __expf(x2), e3 = __expf(x3), e4 = __expf(x4);
    float se  = ((e0 + e1) + (e2 + e3)) + e4;
    float lse = __logf(se);
    float p02 = e0 + e2, p13 = e1 + e3, p24 = e2 + e4, p04 = e0 + e4;
    float xt = (t == 0) ? x0  : (t == 1) ? x1  : (t == 2) ? x2  : (t == 3) ? x3  : x4;
    float et = (t == 0) ? e0  : (t == 1) ? e1  : (t == 2) ? e2  : (t == 3) ? e3  : e4;
    float a  = (t == 0) ? e1  : (t == 1) ? p02 : (t == 2) ? p13 : (t == 3) ? p24 : e3;  // e_{t-1}+e_{t+1}
    float b  = (t == 0) ? e2  : (t == 1) ? e3  : (t == 2) ? p04 : (t == 3) ? e1  : e2;  // e_{t-2}+e_{t+2}
    float u  = fmaf(2.0f, et, fmaf(1.5f, a, b));
    return fmaf(-TPEN, u * __frcp_rn(se), fmaf(-TGT_W, xt, lse));
}

__device__ __forceinline__ float sum4(float4 v) { return (v.x + v.y) + (v.z + v.w); }

__global__ __launch_bounds__(256, 8)   // clamp to 32 regs -> 8 blocks/SM, 64 warps
void bloom_loss_kernel(const float4* __restrict__ in4,
                       const int4*   __restrict__ tgt4,
                       float* __restrict__ out,
                       int nquads, int n, float inv_b) {
    int tq = blockIdx.x * blockDim.x + threadIdx.x;
    float acc = 0.0f;
    if (tq < nquads) {
        // 4 rows = 20 floats = 5 x float4, 16B aligned for every tq
        float4 a = in4[tq * 5 + 0];
        float4 b = in4[tq * 5 + 1];
        float4 c = in4[tq * 5 + 2];
        float4 d = in4[tq * 5 + 3];
        float4 e = in4[tq * 5 + 4];
        int4 tg = tgt4[tq];
        float gs = sum4(a) + sum4(b) + sum4(c) + sum4(d) + sum4(e);
        acc  = row_core(a.x, a.y, a.z, a.w, b.x, tg.x);
        acc += row_core(b.y, b.z, b.w, c.x, c.y, tg.y);
        acc += row_core(c.z, c.w, d.x, d.y, d.z, tg.z);
        acc += row_core(d.w, e.x, e.y, e.z, e.w, tg.w);
        acc = fmaf(-SMOOTH_W, gs, acc) + (4.0f * TPEN * 2.0f);   // +0.2 per row
    }
    // tail rows (n % 4): one thread; not hit when n is a multiple of 4
    if (blockIdx.x == 0 && threadIdx.x == 0) {
        const float* in_s  = (const float*)in4;
        const int*   tgt_s = (const int*)tgt4;
        for (int i = nquads * 4; i < n; i++) {
            const float* x = in_s + (size_t)i * 5;
            float s = ((x[0] + x[1]) + (x[2] + x[3])) + x[4];
            acc += row_core(x[0], x[1], x[2], x[3], x[4], tgt_s[i]);
            acc = fmaf(-SMOOTH_W, s, acc) + (TPEN * 2.0f);
        }
    }
    // warp reduce
    #pragma unroll
    for (int o = 16; o > 0; o >>= 1) acc += __shfl_xor_sync(0xFFFFFFFFu, acc, o);
    __shared__ float ssum[8];
    int lane = threadIdx.x & 31;
    int wid  = threadIdx.x >> 5;
    if (lane == 0) ssum[wid] = acc;
    __syncthreads();
    if (wid == 0) {
        float v = (lane < 8) ? ssum[lane] : 0.0f;
        #pragma unroll
        for (int o = 4; o > 0; o >>= 1) v += __shfl_xor_sync(0xFFFFFFFFu, v, o);
        if (lane == 0) {
            atomicAdd(&g_acc, v);
            __threadfence();
            unsigned int done = atomicAdd(&g_count, 1u);
            if (done == gridDim.x - 1) {
                float tot = atomicAdd(&g_acc, 0.0f);   // coherent read after all adds
                out[0] = tot * inv_b;
                g_acc   = 0.0f;                        // reset for next graph replay
                __threadfence();
                g_count = 0u;
            }
        }
    }
}

extern "C" void kernel_launch(void* const* d_in, const int* in_sizes, int n_in,
                              void* d_out, int out_size) {
    const float* inputs  = (const float*)d_in[0];
    const int*   targets = (const int*)d_in[1];
    float* out = (float*)d_out;

    int n = in_sizes[1];            // B rows
    int nquads = n >> 2;
    float inv_b = 1.0f / (float)n;

    int blocks = (nquads > 0) ? (nquads + 255) / 256 : 1;
    bloom_loss_kernel<<<blocks, 256>>>((const float4*)inputs,
                                       (const int4*)targets,
                                       out, nquads, n, inv_b);
}

// round 11
// speedup vs baseline: 1.3343x; 1.3343x over previous
#include <cuda_runtime.h>

// BloomStageLoss: label-smoothed CE + transition penalty, reduced to scalar.
// inputs:  d_in[0] = float32 [B,5], d_in[1] = int32 [B]; output: float32 [1]
// R3 math (fastest measured) + fence-free packed-atomic single-launch epilogue.

#define NUM_CLASSES 5
#define SMOOTH_OFF 0.025f
#define TGT_W      0.875f
#define TPEN       0.1f

#define PACK_BIAS   32768.0
#define PACK_SCALE  8388608.0            // 2^23
#define PACK_CNT_SH 51

__device__ unsigned long long g_pack;    // zero-init at load; reset by last block each replay

// R3 row loss, verbatim: max-subtracted softmax + per-j transition loop.
__device__ __forceinline__ float row_loss(float x0, float x1, float x2, float x3, float x4, int t) {
    float m = fmaxf(fmaxf(fmaxf(x0, x1), fmaxf(x2, x3)), x4);
    float e0 = __expf(x0 - m);
    float e1 = __expf(x1 - m);
    float e2 = __expf(x2 - m);
    float e3 = __expf(x3 - m);
    float e4 = __expf(x4 - m);
    float se = e0 + e1 + e2 + e3 + e4;
    float lse = m + __logf(se);
    float sumx = x0 + x1 + x2 + x3 + x4;
    float xt = (t == 0) ? x0 : (t == 1) ? x1 : (t == 2) ? x2 : (t == 3) ? x3 : x4;
    float ce = lse - SMOOTH_OFF * sumx - TGT_W * xt;
    float pen = 0.0f;
    #pragma unroll
    for (int j = 0; j < NUM_CLASSES; j++) {
        int d = (t > j) ? (t - j) : (j - t);
        float w = (d <= 2) ? 0.5f * (float)d : 2.0f;
        float e = (j == 0) ? e0 : (j == 1) ? e1 : (j == 2) ? e2 : (j == 3) ? e3 : e4;
        pen += e * w;
    }
    pen *= __frcp_rn(se);
    return ce + TPEN * pen;
}

__global__ __launch_bounds__(256)
void bloom_loss_kernel(const float4* __restrict__ in4,
                       const int4*   __restrict__ tgt4,
                       float* __restrict__ out,
                       int nquads, int n, float inv_b) {
    int tq = blockIdx.x * blockDim.x + threadIdx.x;
    float acc = 0.0f;
    if (tq < nquads) {
        float4 a = in4[tq * 5 + 0];
        float4 b = in4[tq * 5 + 1];
        float4 c = in4[tq * 5 + 2];
        float4 d = in4[tq * 5 + 3];
        float4 e = in4[tq * 5 + 4];
        int4 tg = tgt4[tq];
        acc  = row_loss(a.x, a.y, a.z, a.w, b.x, tg.x);
        acc += row_loss(b.y, b.z, b.w, c.x, c.y, tg.y);
        acc += row_loss(c.z, c.w, d.x, d.y, d.z, tg.z);
        acc += row_loss(d.w, e.x, e.y, e.z, e.w, tg.w);
    }
    // tail rows (n % 4): one thread; not hit when n is a multiple of 4
    if (blockIdx.x == 0 && threadIdx.x == 0) {
        const float* in_s  = (const float*)in4;
        const int*   tgt_s = (const int*)tgt4;
        for (int i = nquads * 4; i < n; i++) {
            const float* x = in_s + (size_t)i * 5;
            acc += row_loss(x[0], x[1], x[2], x[3], x[4], tgt_s[i]);
        }
    }
    // warp reduce
    #pragma unroll
    for (int o = 16; o > 0; o >>= 1) acc += __shfl_xor_sync(0xFFFFFFFFu, acc, o);
    __shared__ float ssum[8];
    int lane = threadIdx.x & 31;
    int wid  = threadIdx.x >> 5;
    if (lane == 0) ssum[wid] = acc;
    __syncthreads();
    if (wid == 0) {
        float v = (lane < 8) ? ssum[lane] : 0.0f;
        #pragma unroll
        for (int o = 4; o > 0; o >>= 1) v += __shfl_xor_sync(0xFFFFFFFFu, v, o);
        if (lane == 0) {
            // One packed atomic: low 51 bits = biased fixed-point sum, high bits = block count.
            // No fence needed: count and sum commit in the same RMW.
            unsigned long long contrib =
                (unsigned long long)llrint(((double)v + PACK_BIAS) * PACK_SCALE)
                | (1ull << PACK_CNT_SH);
            unsigned long long newv = atomicAdd(&g_pack, contrib) + contrib;
            if ((newv >> PACK_CNT_SH) == (unsigned long long)gridDim.x) {
                long long sfix = (long long)(newv & ((1ull << PACK_CNT_SH) - 1ull));
                double tot = (double)sfix * (1.0 / PACK_SCALE)
                           - (double)gridDim.x * PACK_BIAS;
                out[0] = (float)(tot * (double)inv_b);
                g_pack = 0ull;                 // reset for next graph replay
            }
        }
    }
}

extern "C" void kernel_launch(void* const* d_in, const int* in_sizes, int n_in,
                              void* d_out, int out_size) {
    const float* inputs  = (const float*)d_in[0];
    const int*   targets = (const int*)d_in[1];
    float* out = (float*)d_out;

    int n = in_sizes[1];            // B rows
    int nquads = n >> 2;
    float inv_b = 1.0f / (float)n;

    int blocks = (nquads > 0) ? (nquads + 255) / 256 : 1;
    bloom_loss_kernel<<<blocks, 256>>>((const float4*)inputs,
                                       (const int4*)targets,
                                       out, nquads, n, inv_b);
}